// round 13
// baseline (speedup 1.0000x reference)
#include <cuda_runtime.h>
#include <cuda_fp16.h>
#include <math.h>
#include <stdint.h>

#define T_STEPS 512
#define BATCH   64
#define DIM     1024
#define HID     1024
#define GATES   4096
#define NCTA    128

// Scratch (__device__ globals: allocation-free rule)
__device__ float    g_xg[(size_t)T_STEPS * BATCH * GATES]; // x@Wi + b
__device__ __half   g_wrh[(size_t)GATES * DIM];            // Wh reordered [n'][k], fp16
__device__ uint32_t g_hf[2][4 * 64 * 32 * 4];              // h in A-frag layout, ping-pong
__device__ unsigned g_flags[NCTA * 64];                    // per-CTA flag, 256B stride

#define HFBYTES 131072   // one g_hf buffer: 4 m-blocks x 64 q-blocks x 32 lanes x 16B

// ---------------------------------------------------------------------------
// Helpers
// ---------------------------------------------------------------------------
__device__ __forceinline__ uint32_t f2tf(float v) {
    uint32_t u;
    asm("cvt.rna.tf32.f32 %0, %1;" : "=r"(u) : "f"(v));
    return u;
}

__device__ __forceinline__ void mma_tf32(float* c,
                                         uint32_t a0, uint32_t a1, uint32_t a2, uint32_t a3,
                                         uint32_t b0, uint32_t b1) {
    asm volatile(
        "mma.sync.aligned.m16n8k8.row.col.f32.tf32.tf32.f32 "
        "{%0,%1,%2,%3}, {%4,%5,%6,%7}, {%8,%9}, {%0,%1,%2,%3};"
        : "+f"(c[0]), "+f"(c[1]), "+f"(c[2]), "+f"(c[3])
        : "r"(a0), "r"(a1), "r"(a2), "r"(a3), "r"(b0), "r"(b1));
}

__device__ __forceinline__ void mma_f16(float* c,
                                        uint32_t a0, uint32_t a1, uint32_t a2, uint32_t a3,
                                        uint32_t b0, uint32_t b1) {
    asm volatile(
        "mma.sync.aligned.m16n8k16.row.col.f32.f16.f16.f32 "
        "{%0,%1,%2,%3}, {%4,%5,%6,%7}, {%8,%9}, {%0,%1,%2,%3};"
        : "+f"(c[0]), "+f"(c[1]), "+f"(c[2]), "+f"(c[3])
        : "r"(a0), "r"(a1), "r"(a2), "r"(a3), "r"(b0), "r"(b1));
}

__device__ __forceinline__ unsigned ld_acq(const unsigned* p) {
    unsigned v;
    asm volatile("ld.acquire.gpu.global.u32 %0, [%1];" : "=r"(v) : "l"(p));
    return v;
}
__device__ __forceinline__ void st_rel(unsigned* p, unsigned v) {
    asm volatile("st.release.gpu.global.u32 [%0], %1;" :: "l"(p), "r"(v) : "memory");
}

__device__ __forceinline__ uint4 ldcg128(const void* p) {
    uint4 v;
    asm volatile("ld.global.cg.v4.u32 {%0,%1,%2,%3}, [%4];"
                 : "=r"(v.x), "=r"(v.y), "=r"(v.z), "=r"(v.w) : "l"(p));
    return v;
}

__device__ __forceinline__ uint32_t smem_u32(const void* p) {
    uint32_t a;
    asm("{ .reg .u64 t; cvta.to.shared.u64 t, %1; cvt.u32.u64 %0, t; }" : "=r"(a) : "l"(p));
    return a;
}

__device__ __forceinline__ float fsig(float x) { return 1.f / (1.f + __expf(-x)); }
__device__ __forceinline__ float ftanh(float x) {
    float e = __expf(-2.f * fabsf(x));
    float r = (1.f - e) / (1.f + e);
    return x < 0.f ? -r : r;
}

#define LDSM4(r0, r1, r2, r3, addr) \
    asm volatile("ldmatrix.sync.aligned.m8n8.x4.shared.b16 {%0,%1,%2,%3}, [%4];" \
                 : "=r"(r0), "=r"(r1), "=r"(r2), "=r"(r3) : "r"(addr))

// ---------------------------------------------------------------------------
// Kernel 1: xg = x @ Wi + b (tf32, known-good). Fused prep: Wh -> g_wrh
// (fp16, gate-interleaved: np = c*64 + nh*32 + g*8 + jj for
// col = g*1024 + c*16 + nh*8 + jj), h0 -> g_hf[0] (frag layout), reset flags.
// ---------------------------------------------------------------------------
__global__ __launch_bounds__(256) void xg_gemm_mma(const float* __restrict__ x,
                                                   const float* __restrict__ Wi,
                                                   const float* __restrict__ bias,
                                                   const float* __restrict__ Wh,
                                                   const float* __restrict__ h0) {
    {
        int gtid = (blockIdx.y * gridDim.x + blockIdx.x) * 256 + threadIdx.x;
        if (gtid < NCTA) g_flags[gtid * 64] = 0;
        if (gtid < 32768) {  // h0 -> frag layout, one half2 per thread
            int row = gtid >> 9;         // 0..63
            int col = (gtid & 511) * 2;  // even col
            int m = row >> 4, q = col >> 4, kin = col & 15;
            int lane = ((row & 7) << 2) | ((kin & 7) >> 1);
            int reg = ((row & 15) >> 3) | ((kin >> 3) << 1);
            __half2 hh = __floats2half2_rn(h0[row * HID + col], h0[row * HID + col + 1]);
            *(uint32_t*)((char*)g_hf + ((size_t)((m * 64 + q) * 32 + lane)) * 16 + reg * 4) =
                *(uint32_t*)&hh;
        }
#pragma unroll
        for (int e = 0; e < 2; e++) {
            int idx = e * (DIM * GATES / 2) + gtid;
            int col = idx & 4095, k = idx >> 12;
            int g = col >> 10, rem = col & 1023;
            int c = rem >> 4, r2 = rem & 15, nhp = r2 >> 3, jj = r2 & 7;
            int np = c * 64 + nhp * 32 + g * 8 + jj;
            g_wrh[(size_t)np * DIM + k] = __float2half_rn(Wh[idx]);
        }
    }

    __shared__ uint32_t As[128][36];
    __shared__ uint32_t Bs[32][132];

    int tid = threadIdx.x, wid = tid >> 5, lane = tid & 31;
    int gid = lane >> 2, tig = lane & 3;
    int bm = blockIdx.y * 128, bn = blockIdx.x * 128;
    int wrow = (wid & 3) * 32, wcol = (wid >> 2) * 64;

    float acc[2][8][4];
#pragma unroll
    for (int i = 0; i < 2; i++)
#pragma unroll
        for (int j = 0; j < 8; j++)
#pragma unroll
            for (int k = 0; k < 4; k++) acc[i][j][k] = 0.f;

    float4 pa[4], pb[4];

#pragma unroll
    for (int u = 0; u < 4; u++) {
        int s = u * 256 + tid, r = s >> 3, cc = (s & 7) * 4;
        pa[u] = *(const float4*)(x + (size_t)(bm + r) * DIM + cc);
    }
#pragma unroll
    for (int u = 0; u < 4; u++) {
        int s = u * 256 + tid, r = s >> 5, cc = (s & 31) * 4;
        pb[u] = *(const float4*)(Wi + (size_t)r * GATES + bn + cc);
    }

    for (int k0 = 0; k0 < DIM; k0 += 32) {
#pragma unroll
        for (int u = 0; u < 4; u++) {
            int s = u * 256 + tid, r = s >> 3, cc = (s & 7) * 4;
            As[r][cc + 0] = f2tf(pa[u].x); As[r][cc + 1] = f2tf(pa[u].y);
            As[r][cc + 2] = f2tf(pa[u].z); As[r][cc + 3] = f2tf(pa[u].w);
        }
#pragma unroll
        for (int u = 0; u < 4; u++) {
            int s = u * 256 + tid, r = s >> 5, cc = (s & 31) * 4;
            Bs[r][cc + 0] = f2tf(pb[u].x); Bs[r][cc + 1] = f2tf(pb[u].y);
            Bs[r][cc + 2] = f2tf(pb[u].z); Bs[r][cc + 3] = f2tf(pb[u].w);
        }
        __syncthreads();

        if (k0 + 32 < DIM) {
#pragma unroll
            for (int u = 0; u < 4; u++) {
                int s = u * 256 + tid, r = s >> 3, cc = (s & 7) * 4;
                pa[u] = *(const float4*)(x + (size_t)(bm + r) * DIM + k0 + 32 + cc);
            }
#pragma unroll
            for (int u = 0; u < 4; u++) {
                int s = u * 256 + tid, r = s >> 5, cc = (s & 31) * 4;
                pb[u] = *(const float4*)(Wi + (size_t)(k0 + 32 + r) * GATES + bn + cc);
            }
        }

#pragma unroll
        for (int kk = 0; kk < 4; kk++) {
            int kb = kk * 8;
            uint32_t a[2][4];
#pragma unroll
            for (int mf = 0; mf < 2; mf++) {
                int m = wrow + mf * 16 + gid;
                a[mf][0] = As[m][kb + tig];
                a[mf][1] = As[m + 8][kb + tig];
                a[mf][2] = As[m][kb + tig + 4];
                a[mf][3] = As[m + 8][kb + tig + 4];
            }
#pragma unroll
            for (int nf = 0; nf < 8; nf++) {
                uint32_t b0 = Bs[kb + tig][wcol + nf * 8 + gid];
                uint32_t b1 = Bs[kb + tig + 4][wcol + nf * 8 + gid];
                mma_tf32(acc[0][nf], a[0][0], a[0][1], a[0][2], a[0][3], b0, b1);
                mma_tf32(acc[1][nf], a[1][0], a[1][1], a[1][2], a[1][3], b0, b1);
            }
        }
        __syncthreads();
    }

#pragma unroll
    for (int mf = 0; mf < 2; mf++)
#pragma unroll
        for (int nf = 0; nf < 8; nf++) {
            int row = bm + wrow + mf * 16 + gid;
            int col = bn + wcol + nf * 8 + 2 * tig;
            float bv0 = bias[col], bv1 = bias[col + 1];
            g_xg[(size_t)row * GATES + col]           = acc[mf][nf][0] + bv0;
            g_xg[(size_t)row * GATES + col + 1]       = acc[mf][nf][1] + bv1;
            g_xg[(size_t)(row + 8) * GATES + col]     = acc[mf][nf][2] + bv0;
            g_xg[(size_t)(row + 8) * GATES + col + 1] = acc[mf][nf][3] + bv1;
        }
}

// ---------------------------------------------------------------------------
// Kernel 2: persistent recurrence, A direct-from-gmem in fragment layout.
// CTA (c = bid>>1, mg = bid&1): batch rows [mg*32,+32) x h-cols [c*16,+16) x
// 4 gates (N=64). 8 warps = 8-way K-split (warp ks owns k16 blocks
// q in [ks*8, ks*8+8)). Per-warp flag waits on its 8 producers only.
// B resident in smem (128 KB); reduce buffer 68 KB; no A smem tile.
// ---------------------------------------------------------------------------
#define BBYTES 131072                 // B: 64 n-rows x 2048 B, XOR swizzled
#define CHSZ   544                    // reduce chunk stride (512 data + pad)
#define RWSZ   (16 * CHSZ)            // per-warp reduce: 16 chunks (mf*8+nf)
#define REDOFF BBYTES
#define PERSIST_SMEM (REDOFF + 8 * RWSZ)   // 131072 + 69632 = 200704

__global__ __launch_bounds__(256, 1) void lstm_persist(const float* __restrict__ c0,
                                                       float* __restrict__ out) {
    extern __shared__ uint32_t sm[];
    char* smc = (char*)sm;
    uint32_t sbase = smem_u32(sm);

    int tid = threadIdx.x, wid = tid >> 5, lane = tid & 31;
    int cta = blockIdx.x;
    int c = cta >> 1, mg = cta & 1;
    int ks = wid;                      // this warp's K-eighth
    int n0 = c * 64;

    // ---- stationary B fill: 64 rows x 2048 B, XOR swizzled ----
#pragma unroll 4
    for (int u = 0; u < 32; u++) {
        int idx = u * 256 + tid;
        int n = idx >> 7, seg = idx & 127;
        uint4 v = *(const uint4*)((const char*)g_wrh + ((size_t)(n0 + n) * DIM + seg * 8) * 2);
        *(uint4*)(smc + n * 2048 + ((seg * 16) ^ ((n & 7) * 16))) = v;
    }

    // ---- B ldmatrix addressing (4 LDSM4 per k16: n-rows 0,16,32,48) ----
    int ri = lane & 7;
    uint32_t kbB = (uint32_t)(((lane >> 3) & 1) * 16);
    uint32_t bOff[4], bSw[4];
#pragma unroll
    for (int j = 0; j < 4; j++) {
        int nrow = j * 16 + ((lane >> 4) & 1) * 8 + ri;
        bOff[j] = (uint32_t)(nrow * 2048);
        bSw[j] = (uint32_t)((nrow & 7) * 16);
    }

    // ---- epilogue constants (every thread owns 2 h-cells) ----
    int rl = wid * 4 + (lane >> 3);        // local row 0..31
    int rgl = mg * 32 + rl;                // global batch row
    int nh_t = (lane >> 2) & 1;
    int jj0 = (lane & 3) * 2;
    int hc = c * 16 + nh_t * 8 + jj0;      // global h col (pair hc, hc+1)
    int mfE = rl >> 4, rf = rl & 15;
    int dlane = (rf & 7) * 4 + (jj0 >> 1);
    int fb = (rf >> 3) * 2;                // D-frag float index base
    int regE = (rf >> 3) | (nh_t << 1);    // A-frag reg index for h store
    uint32_t hfStoreOff =
        (uint32_t)(((mg * 2 + mfE) * 64 + c) * 32 + dlane) * 16 + regE * 4;

    float creg[2];
    creg[0] = c0[(size_t)rgl * HID + hc];
    creg[1] = c0[(size_t)rgl * HID + hc + 1];
    float xv[8];
#pragma unroll
    for (int g = 0; g < 4; g++) {
        xv[g * 2 + 0] = g_xg[(size_t)rgl * GATES + g * 1024 + hc];
        xv[g * 2 + 1] = g_xg[(size_t)rgl * GATES + g * 1024 + hc + 1];
    }
    __syncthreads();   // B resident

    for (int t = 0; t < T_STEPS; t++) {
        // ---- per-warp wait: only THIS warp's 8 producers ----
        if (t > 0) {
            if (lane < 8) {
                const unsigned* fp = &g_flags[(((ks * 8 + lane) << 1) | mg) << 6];
                while (ld_acq(fp) < (unsigned)t) { }
            }
            __syncwarp();
        }

        const char* hb = (const char*)g_hf + (size_t)(t & 1) * HFBYTES;

        // ---- A prefetch pipeline (depth 3), frags direct from gmem ----
        uint4 pa[3][2];
#pragma unroll
        for (int p = 0; p < 3; p++) {
            int q = ks * 8 + p;
#pragma unroll
            for (int mf = 0; mf < 2; mf++)
                pa[p][mf] = ldcg128(hb +
                    (size_t)(((mg * 2 + mf) * 64 + q) * 32 + lane) * 16);
        }

        float acc[2][8][4];
#pragma unroll
        for (int i = 0; i < 2; i++)
#pragma unroll
            for (int j = 0; j < 8; j++)
#pragma unroll
                for (int k = 0; k < 4; k++) acc[i][j][k] = 0.f;

#pragma unroll
        for (int kq = 0; kq < 8; kq++) {
            uint4 A0 = pa[kq % 3][0], A1 = pa[kq % 3][1];
            if (kq < 5) {
                int qn = ks * 8 + kq + 3;
#pragma unroll
                for (int mf = 0; mf < 2; mf++)
                    pa[kq % 3][mf] = ldcg128(hb +
                        (size_t)(((mg * 2 + mf) * 64 + qn) * 32 + lane) * 16);
            }
            int q = ks * 8 + kq;
            uint32_t kB = (uint32_t)(q * 32) + kbB;
            uint32_t bq[16];
#pragma unroll
            for (int j = 0; j < 4; j++)
                LDSM4(bq[j * 4], bq[j * 4 + 1], bq[j * 4 + 2], bq[j * 4 + 3],
                      sbase + bOff[j] + (kB ^ bSw[j]));
#pragma unroll
            for (int nf = 0; nf < 8; nf++) {
                mma_f16(acc[0][nf], A0.x, A0.y, A0.z, A0.w, bq[nf * 2], bq[nf * 2 + 1]);
                mma_f16(acc[1][nf], A1.x, A1.y, A1.z, A1.w, bq[nf * 2], bq[nf * 2 + 1]);
            }
        }

        // ---- partial stores: red[warp][mf*8+nf][lane] float4 ----
        {
            char* rp = smc + REDOFF + wid * RWSZ + lane * 16;
#pragma unroll
            for (int mf = 0; mf < 2; mf++)
#pragma unroll
                for (int nf = 0; nf < 8; nf++)
                    *(float4*)(rp + (mf * 8 + nf) * CHSZ) = *(const float4*)acc[mf][nf];
        }
        __syncthreads();

        // ---- reduce (8-way) + fused epilogue, ALL 256 threads ----
        float sg[4][2];
#pragma unroll
        for (int g = 0; g < 4; g++) { sg[g][0] = 0.f; sg[g][1] = 0.f; }
#pragma unroll
        for (int w = 0; w < 8; w++) {
            const char* rp = smc + REDOFF + w * RWSZ +
                             (mfE * 8 + nh_t * 4) * CHSZ + dlane * 16 + fb * 4;
#pragma unroll
            for (int g = 0; g < 4; g++) {
                float2 v = *(const float2*)(rp + g * CHSZ);
                sg[g][0] += v.x; sg[g][1] += v.y;
            }
        }

        float hv[2];
#pragma unroll
        for (int cc = 0; cc < 2; cc++) {
            float iv = fsig(sg[0][cc] + xv[cc]);
            float fv = fsig(sg[1][cc] + xv[2 + cc]);
            float gv = ftanh(sg[2][cc] + xv[4 + cc]);
            float ov = fsig(sg[3][cc] + xv[6 + cc]);
            float cv = fv * creg[cc] + iv * gv;
            creg[cc] = cv;
            hv[cc] = ov * ftanh(cv);
        }

        // h -> frag layout (one STG.32) for step t+1 consumers
        {
            __half2 hh = __floats2half2_rn(hv[0], hv[1]);
            *(uint32_t*)((char*)g_hf + (size_t)((t + 1) & 1) * HFBYTES + hfStoreOff) =
                *(uint32_t*)&hh;
        }
        __syncthreads();   // all epilogue stores done; red consumable next step
        if (tid == 0 && t + 1 < T_STEPS)
            st_rel(&g_flags[cta << 6], (unsigned)(t + 1));

        // fp32 output + next xg prefetch (off the release path)
        *(float2*)(out + (size_t)t * BATCH * HID + (size_t)rgl * HID + hc) =
            make_float2(hv[0], hv[1]);
        if (t + 1 < T_STEPS) {
            const float* xn = g_xg + (size_t)(t + 1) * BATCH * GATES + (size_t)rgl * GATES;
#pragma unroll
            for (int g = 0; g < 4; g++) {
                xv[g * 2 + 0] = xn[g * 1024 + hc];
                xv[g * 2 + 1] = xn[g * 1024 + hc + 1];
            }
        }
    }
}

// ---------------------------------------------------------------------------
extern "C" void kernel_launch(void* const* d_in, const int* in_sizes, int n_in,
                              void* d_out, int out_size) {
    const float* x  = (const float*)d_in[0];   // [T, B, D]
    const float* c0 = (const float*)d_in[1];   // [B, H]
    const float* h0 = (const float*)d_in[2];   // [B, H]
    const float* Wi = (const float*)d_in[3];   // [D, 4H]
    const float* Wh = (const float*)d_in[4];   // [H, 4H]
    const float* b  = (const float*)d_in[5];   // [4H]
    float* out = (float*)d_out;                // [T, B, H]

    cudaFuncSetAttribute(lstm_persist, cudaFuncAttributeMaxDynamicSharedMemorySize,
                         PERSIST_SMEM);

    // Input projection + fused prep (Wh->fp16 reorder, h0->frags, flag reset)
    dim3 g1(GATES / 128, (T_STEPS * BATCH) / 128);
    xg_gemm_mma<<<g1, 256>>>(x, Wi, b, Wh, h0);

    // Persistent recurrence: one launch, all 512 steps
    lstm_persist<<<NCTA, 256, PERSIST_SMEM>>>(c0, out);
}

// round 14
// speedup vs baseline: 1.0040x; 1.0040x over previous
#include <cuda_runtime.h>
#include <cuda_fp16.h>
#include <math.h>
#include <stdint.h>

#define T_STEPS 512
#define BATCH   64
#define DIM     1024
#define HID     1024
#define GATES   4096
#define NCTA    128

// Scratch (__device__ globals: allocation-free rule)
__device__ float    g_xg[(size_t)T_STEPS * BATCH * GATES]; // x@Wi + b
__device__ __half   g_wrh[(size_t)GATES * DIM];            // Wh reordered [n'][k], fp16
__device__ uint32_t g_hf[2][4 * 64 * 32 * 4];              // h in A-frag layout, ping-pong
__device__ unsigned g_flags[NCTA * 64];                    // per-CTA flag, 256B stride

#define HFBYTES 131072   // one g_hf buffer: 4 m-blocks x 64 q-blocks x 32 lanes x 16B

// ---------------------------------------------------------------------------
// Helpers
// ---------------------------------------------------------------------------
__device__ __forceinline__ uint32_t f2tf(float v) {
    uint32_t u;
    asm("cvt.rna.tf32.f32 %0, %1;" : "=r"(u) : "f"(v));
    return u;
}

__device__ __forceinline__ void mma_tf32(float* c,
                                         uint32_t a0, uint32_t a1, uint32_t a2, uint32_t a3,
                                         uint32_t b0, uint32_t b1) {
    asm volatile(
        "mma.sync.aligned.m16n8k8.row.col.f32.tf32.tf32.f32 "
        "{%0,%1,%2,%3}, {%4,%5,%6,%7}, {%8,%9}, {%0,%1,%2,%3};"
        : "+f"(c[0]), "+f"(c[1]), "+f"(c[2]), "+f"(c[3])
        : "r"(a0), "r"(a1), "r"(a2), "r"(a3), "r"(b0), "r"(b1));
}

__device__ __forceinline__ void mma_f16(float* c,
                                        uint32_t a0, uint32_t a1, uint32_t a2, uint32_t a3,
                                        uint32_t b0, uint32_t b1) {
    asm volatile(
        "mma.sync.aligned.m16n8k16.row.col.f32.f16.f16.f32 "
        "{%0,%1,%2,%3}, {%4,%5,%6,%7}, {%8,%9}, {%0,%1,%2,%3};"
        : "+f"(c[0]), "+f"(c[1]), "+f"(c[2]), "+f"(c[3])
        : "r"(a0), "r"(a1), "r"(a2), "r"(a3), "r"(b0), "r"(b1));
}

__device__ __forceinline__ unsigned ld_acq(const unsigned* p) {
    unsigned v;
    asm volatile("ld.acquire.gpu.global.u32 %0, [%1];" : "=r"(v) : "l"(p));
    return v;
}
__device__ __forceinline__ void st_rel(unsigned* p, unsigned v) {
    asm volatile("st.release.gpu.global.u32 [%0], %1;" :: "l"(p), "r"(v) : "memory");
}

__device__ __forceinline__ uint4 ldcg128(const void* p) {
    uint4 v;
    asm volatile("ld.global.cg.v4.u32 {%0,%1,%2,%3}, [%4];"
                 : "=r"(v.x), "=r"(v.y), "=r"(v.z), "=r"(v.w) : "l"(p));
    return v;
}

__device__ __forceinline__ uint32_t smem_u32(const void* p) {
    uint32_t a;
    asm("{ .reg .u64 t; cvta.to.shared.u64 t, %1; cvt.u32.u64 %0, t; }" : "=r"(a) : "l"(p));
    return a;
}

__device__ __forceinline__ float fsig(float x) { return 1.f / (1.f + __expf(-x)); }
__device__ __forceinline__ float ftanh(float x) {
    float e = __expf(-2.f * fabsf(x));
    float r = (1.f - e) / (1.f + e);
    return x < 0.f ? -r : r;
}

#define LDSM4(r0, r1, r2, r3, addr) \
    asm volatile("ldmatrix.sync.aligned.m8n8.x4.shared.b16 {%0,%1,%2,%3}, [%4];" \
                 : "=r"(r0), "=r"(r1), "=r"(r2), "=r"(r3) : "r"(addr))

// ---------------------------------------------------------------------------
// Kernel 1: xg = x @ Wi + b (tf32, known-good). Fused prep: Wh -> g_wrh
// (fp16, gate-interleaved: np = c*64 + nh*32 + g*8 + jj for
// col = g*1024 + c*16 + nh*8 + jj), h0 -> g_hf[0] (frag layout), reset flags.
// ---------------------------------------------------------------------------
__global__ __launch_bounds__(256) void xg_gemm_mma(const float* __restrict__ x,
                                                   const float* __restrict__ Wi,
                                                   const float* __restrict__ bias,
                                                   const float* __restrict__ Wh,
                                                   const float* __restrict__ h0) {
    {
        int gtid = (blockIdx.y * gridDim.x + blockIdx.x) * 256 + threadIdx.x;
        if (gtid < NCTA) g_flags[gtid * 64] = 0;
        if (gtid < 32768) {  // h0 -> frag layout, one half2 per thread
            int row = gtid >> 9;         // 0..63
            int col = (gtid & 511) * 2;  // even col
            int m = row >> 4, q = col >> 4, kin = col & 15;
            int lane = ((row & 7) << 2) | ((kin & 7) >> 1);
            int reg = ((row & 15) >> 3) | ((kin >> 3) << 1);
            __half2 hh = __floats2half2_rn(h0[row * HID + col], h0[row * HID + col + 1]);
            *(uint32_t*)((char*)g_hf + ((size_t)((m * 64 + q) * 32 + lane)) * 16 + reg * 4) =
                *(uint32_t*)&hh;
        }
#pragma unroll
        for (int e = 0; e < 2; e++) {
            int idx = e * (DIM * GATES / 2) + gtid;
            int col = idx & 4095, k = idx >> 12;
            int g = col >> 10, rem = col & 1023;
            int c = rem >> 4, r2 = rem & 15, nhp = r2 >> 3, jj = r2 & 7;
            int np = c * 64 + nhp * 32 + g * 8 + jj;
            g_wrh[(size_t)np * DIM + k] = __float2half_rn(Wh[idx]);
        }
    }

    __shared__ uint32_t As[128][36];
    __shared__ uint32_t Bs[32][132];

    int tid = threadIdx.x, wid = tid >> 5, lane = tid & 31;
    int gid = lane >> 2, tig = lane & 3;
    int bm = blockIdx.y * 128, bn = blockIdx.x * 128;
    int wrow = (wid & 3) * 32, wcol = (wid >> 2) * 64;

    float acc[2][8][4];
#pragma unroll
    for (int i = 0; i < 2; i++)
#pragma unroll
        for (int j = 0; j < 8; j++)
#pragma unroll
            for (int k = 0; k < 4; k++) acc[i][j][k] = 0.f;

    float4 pa[4], pb[4];

#pragma unroll
    for (int u = 0; u < 4; u++) {
        int s = u * 256 + tid, r = s >> 3, cc = (s & 7) * 4;
        pa[u] = *(const float4*)(x + (size_t)(bm + r) * DIM + cc);
    }
#pragma unroll
    for (int u = 0; u < 4; u++) {
        int s = u * 256 + tid, r = s >> 5, cc = (s & 31) * 4;
        pb[u] = *(const float4*)(Wi + (size_t)r * GATES + bn + cc);
    }

    for (int k0 = 0; k0 < DIM; k0 += 32) {
#pragma unroll
        for (int u = 0; u < 4; u++) {
            int s = u * 256 + tid, r = s >> 3, cc = (s & 7) * 4;
            As[r][cc + 0] = f2tf(pa[u].x); As[r][cc + 1] = f2tf(pa[u].y);
            As[r][cc + 2] = f2tf(pa[u].z); As[r][cc + 3] = f2tf(pa[u].w);
        }
#pragma unroll
        for (int u = 0; u < 4; u++) {
            int s = u * 256 + tid, r = s >> 5, cc = (s & 31) * 4;
            Bs[r][cc + 0] = f2tf(pb[u].x); Bs[r][cc + 1] = f2tf(pb[u].y);
            Bs[r][cc + 2] = f2tf(pb[u].z); Bs[r][cc + 3] = f2tf(pb[u].w);
        }
        __syncthreads();

        if (k0 + 32 < DIM) {
#pragma unroll
            for (int u = 0; u < 4; u++) {
                int s = u * 256 + tid, r = s >> 3, cc = (s & 7) * 4;
                pa[u] = *(const float4*)(x + (size_t)(bm + r) * DIM + k0 + 32 + cc);
            }
#pragma unroll
            for (int u = 0; u < 4; u++) {
                int s = u * 256 + tid, r = s >> 5, cc = (s & 31) * 4;
                pb[u] = *(const float4*)(Wi + (size_t)(k0 + 32 + r) * GATES + bn + cc);
            }
        }

#pragma unroll
        for (int kk = 0; kk < 4; kk++) {
            int kb = kk * 8;
            uint32_t a[2][4];
#pragma unroll
            for (int mf = 0; mf < 2; mf++) {
                int m = wrow + mf * 16 + gid;
                a[mf][0] = As[m][kb + tig];
                a[mf][1] = As[m + 8][kb + tig];
                a[mf][2] = As[m][kb + tig + 4];
                a[mf][3] = As[m + 8][kb + tig + 4];
            }
#pragma unroll
            for (int nf = 0; nf < 8; nf++) {
                uint32_t b0 = Bs[kb + tig][wcol + nf * 8 + gid];
                uint32_t b1 = Bs[kb + tig + 4][wcol + nf * 8 + gid];
                mma_tf32(acc[0][nf], a[0][0], a[0][1], a[0][2], a[0][3], b0, b1);
                mma_tf32(acc[1][nf], a[1][0], a[1][1], a[1][2], a[1][3], b0, b1);
            }
        }
        __syncthreads();
    }

#pragma unroll
    for (int mf = 0; mf < 2; mf++)
#pragma unroll
        for (int nf = 0; nf < 8; nf++) {
            int row = bm + wrow + mf * 16 + gid;
            int col = bn + wcol + nf * 8 + 2 * tig;
            float bv0 = bias[col], bv1 = bias[col + 1];
            g_xg[(size_t)row * GATES + col]           = acc[mf][nf][0] + bv0;
            g_xg[(size_t)row * GATES + col + 1]       = acc[mf][nf][1] + bv1;
            g_xg[(size_t)(row + 8) * GATES + col]     = acc[mf][nf][2] + bv0;
            g_xg[(size_t)(row + 8) * GATES + col + 1] = acc[mf][nf][3] + bv1;
        }
}

// ---------------------------------------------------------------------------
// Kernel 2: persistent recurrence, A direct-from-gmem in fragment layout.
// CTA (c = bid>>1, mg = bid&1): batch rows [mg*32,+32) x h-cols [c*16,+16) x
// 4 gates (N=64). 8 warps = 8-way K-split (warp ks owns k16 blocks
// q in [ks*8, ks*8+8)). Per-warp flag waits on its 8 producers only.
// B resident in smem (128 KB); reduce buffer 68 KB; no A smem tile.
// ---------------------------------------------------------------------------
#define BBYTES 131072                 // B: 64 n-rows x 2048 B, XOR swizzled
#define CHSZ   544                    // reduce chunk stride (512 data + pad)
#define RWSZ   (16 * CHSZ)            // per-warp reduce: 16 chunks (mf*8+nf)
#define REDOFF BBYTES
#define PERSIST_SMEM (REDOFF + 8 * RWSZ)   // 131072 + 69632 = 200704

__global__ __launch_bounds__(256, 1) void lstm_persist(const float* __restrict__ c0,
                                                       float* __restrict__ out) {
    extern __shared__ uint32_t sm[];
    char* smc = (char*)sm;
    uint32_t sbase = smem_u32(sm);

    int tid = threadIdx.x, wid = tid >> 5, lane = tid & 31;
    int cta = blockIdx.x;
    int c = cta >> 1, mg = cta & 1;
    int ks = wid;                      // this warp's K-eighth
    int n0 = c * 64;

    // ---- stationary B fill: 64 rows x 2048 B, XOR swizzled ----
#pragma unroll 4
    for (int u = 0; u < 32; u++) {
        int idx = u * 256 + tid;
        int n = idx >> 7, seg = idx & 127;
        uint4 v = *(const uint4*)((const char*)g_wrh + ((size_t)(n0 + n) * DIM + seg * 8) * 2);
        *(uint4*)(smc + n * 2048 + ((seg * 16) ^ ((n & 7) * 16))) = v;
    }

    // ---- B ldmatrix addressing (4 LDSM4 per k16: n-rows 0,16,32,48) ----
    int ri = lane & 7;
    uint32_t kbB = (uint32_t)(((lane >> 3) & 1) * 16);
    uint32_t bOff[4], bSw[4];
#pragma unroll
    for (int j = 0; j < 4; j++) {
        int nrow = j * 16 + ((lane >> 4) & 1) * 8 + ri;
        bOff[j] = (uint32_t)(nrow * 2048);
        bSw[j] = (uint32_t)((nrow & 7) * 16);
    }

    // ---- epilogue constants (every thread owns 2 h-cells) ----
    int rl = wid * 4 + (lane >> 3);        // local row 0..31
    int rgl = mg * 32 + rl;                // global batch row
    int nh_t = (lane >> 2) & 1;
    int jj0 = (lane & 3) * 2;
    int hc = c * 16 + nh_t * 8 + jj0;      // global h col (pair hc, hc+1)
    int mfE = rl >> 4, rf = rl & 15;
    int dlane = (rf & 7) * 4 + (jj0 >> 1);
    int fb = (rf >> 3) * 2;                // D-frag float index base
    int regE = (rf >> 3) | (nh_t << 1);    // A-frag reg index for h store
    uint32_t hfStoreOff =
        (uint32_t)(((mg * 2 + mfE) * 64 + c) * 32 + dlane) * 16 + regE * 4;

    float creg[2];
    creg[0] = c0[(size_t)rgl * HID + hc];
    creg[1] = c0[(size_t)rgl * HID + hc + 1];
    float xv[8];
#pragma unroll
    for (int g = 0; g < 4; g++) {
        xv[g * 2 + 0] = g_xg[(size_t)rgl * GATES + g * 1024 + hc];
        xv[g * 2 + 1] = g_xg[(size_t)rgl * GATES + g * 1024 + hc + 1];
    }
    __syncthreads();   // B resident

    for (int t = 0; t < T_STEPS; t++) {
        // ---- per-warp wait: only THIS warp's 8 producers ----
        if (t > 0) {
            if (lane < 8) {
                const unsigned* fp = &g_flags[(((ks * 8 + lane) << 1) | mg) << 6];
                while (ld_acq(fp) < (unsigned)t) { }
            }
            __syncwarp();
        }

        const char* hb = (const char*)g_hf + (size_t)(t & 1) * HFBYTES;

        // ---- A prefetch pipeline (depth 3), frags direct from gmem ----
        uint4 pa[3][2];
#pragma unroll
        for (int p = 0; p < 3; p++) {
            int q = ks * 8 + p;
#pragma unroll
            for (int mf = 0; mf < 2; mf++)
                pa[p][mf] = ldcg128(hb +
                    (size_t)(((mg * 2 + mf) * 64 + q) * 32 + lane) * 16);
        }

        float acc[2][8][4];
#pragma unroll
        for (int i = 0; i < 2; i++)
#pragma unroll
            for (int j = 0; j < 8; j++)
#pragma unroll
                for (int k = 0; k < 4; k++) acc[i][j][k] = 0.f;

#pragma unroll
        for (int kq = 0; kq < 8; kq++) {
            uint4 A0 = pa[kq % 3][0], A1 = pa[kq % 3][1];
            if (kq < 5) {
                int qn = ks * 8 + kq + 3;
#pragma unroll
                for (int mf = 0; mf < 2; mf++)
                    pa[kq % 3][mf] = ldcg128(hb +
                        (size_t)(((mg * 2 + mf) * 64 + qn) * 32 + lane) * 16);
            }
            int q = ks * 8 + kq;
            uint32_t kB = (uint32_t)(q * 32) + kbB;
            uint32_t bq[16];
#pragma unroll
            for (int j = 0; j < 4; j++)
                LDSM4(bq[j * 4], bq[j * 4 + 1], bq[j * 4 + 2], bq[j * 4 + 3],
                      sbase + bOff[j] + (kB ^ bSw[j]));
#pragma unroll
            for (int nf = 0; nf < 8; nf++) {
                mma_f16(acc[0][nf], A0.x, A0.y, A0.z, A0.w, bq[nf * 2], bq[nf * 2 + 1]);
                mma_f16(acc[1][nf], A1.x, A1.y, A1.z, A1.w, bq[nf * 2], bq[nf * 2 + 1]);
            }
        }

        // ---- partial stores: red[warp][mf*8+nf][lane] float4 ----
        {
            char* rp = smc + REDOFF + wid * RWSZ + lane * 16;
#pragma unroll
            for (int mf = 0; mf < 2; mf++)
#pragma unroll
                for (int nf = 0; nf < 8; nf++)
                    *(float4*)(rp + (mf * 8 + nf) * CHSZ) = *(const float4*)acc[mf][nf];
        }
        __syncthreads();

        // ---- reduce (8-way) + fused epilogue, ALL 256 threads ----
        float sg[4][2];
#pragma unroll
        for (int g = 0; g < 4; g++) { sg[g][0] = 0.f; sg[g][1] = 0.f; }
#pragma unroll
        for (int w = 0; w < 8; w++) {
            const char* rp = smc + REDOFF + w * RWSZ +
                             (mfE * 8 + nh_t * 4) * CHSZ + dlane * 16 + fb * 4;
#pragma unroll
            for (int g = 0; g < 4; g++) {
                float2 v = *(const float2*)(rp + g * CHSZ);
                sg[g][0] += v.x; sg[g][1] += v.y;
            }
        }

        float hv[2];
#pragma unroll
        for (int cc = 0; cc < 2; cc++) {
            float iv = fsig(sg[0][cc] + xv[cc]);
            float fv = fsig(sg[1][cc] + xv[2 + cc]);
            float gv = ftanh(sg[2][cc] + xv[4 + cc]);
            float ov = fsig(sg[3][cc] + xv[6 + cc]);
            float cv = fv * creg[cc] + iv * gv;
            creg[cc] = cv;
            hv[cc] = ov * ftanh(cv);
        }

        // h -> frag layout (one STG.32) for step t+1 consumers
        {
            __half2 hh = __floats2half2_rn(hv[0], hv[1]);
            *(uint32_t*)((char*)g_hf + (size_t)((t + 1) & 1) * HFBYTES + hfStoreOff) =
                *(uint32_t*)&hh;
        }
        __syncthreads();   // all epilogue stores done; red consumable next step
        if (tid == 0 && t + 1 < T_STEPS)
            st_rel(&g_flags[cta << 6], (unsigned)(t + 1));

        // fp32 output + next xg prefetch (off the release path)
        *(float2*)(out + (size_t)t * BATCH * HID + (size_t)rgl * HID + hc) =
            make_float2(hv[0], hv[1]);
        if (t + 1 < T_STEPS) {
            const float* xn = g_xg + (size_t)(t + 1) * BATCH * GATES + (size_t)rgl * GATES;
#pragma unroll
            for (int g = 0; g < 4; g++) {
                xv[g * 2 + 0] = xn[g * 1024 + hc];
                xv[g * 2 + 1] = xn[g * 1024 + hc + 1];
            }
        }
    }
}

// ---------------------------------------------------------------------------
extern "C" void kernel_launch(void* const* d_in, const int* in_sizes, int n_in,
                              void* d_out, int out_size) {
    const float* x  = (const float*)d_in[0];   // [T, B, D]
    const float* c0 = (const float*)d_in[1];   // [B, H]
    const float* h0 = (const float*)d_in[2];   // [B, H]
    const float* Wi = (const float*)d_in[3];   // [D, 4H]
    const float* Wh = (const float*)d_in[4];   // [H, 4H]
    const float* b  = (const float*)d_in[5];   // [4H]
    float* out = (float*)d_out;                // [T, B, H]

    cudaFuncSetAttribute(lstm_persist, cudaFuncAttributeMaxDynamicSharedMemorySize,
                         PERSIST_SMEM);

    // Input projection + fused prep (Wh->fp16 reorder, h0->frags, flag reset)
    dim3 g1(GATES / 128, (T_STEPS * BATCH) / 128);
    xg_gemm_mma<<<g1, 256>>>(x, Wi, b, Wh, h0);

    // Persistent recurrence: one launch, all 512 steps
    lstm_persist<<<NCTA, 256, PERSIST_SMEM>>>(c0, out);
}

// round 15
// speedup vs baseline: 1.0054x; 1.0014x over previous
#include <cuda_runtime.h>
#include <cuda_fp16.h>
#include <math.h>
#include <stdint.h>

#define T_STEPS 512
#define BATCH   64
#define DIM     1024
#define HID     1024
#define GATES   4096
#define NCTA    128

// Scratch (__device__ globals: allocation-free rule)
__device__ float    g_xg[(size_t)T_STEPS * BATCH * GATES]; // x@Wi + b
__device__ __half   g_wrh[(size_t)GATES * DIM];            // Wh reordered [n'][k], fp16
__device__ uint32_t g_hf[2][4 * 64 * 32 * 4];              // h in A-frag layout, ping-pong
__device__ unsigned g_flags[NCTA * 64];                    // per-CTA flag, 256B stride

#define HFBYTES 131072   // one g_hf buffer: 4 m-blocks x 64 q-blocks x 32 lanes x 16B

// ---------------------------------------------------------------------------
// Helpers
// ---------------------------------------------------------------------------
__device__ __forceinline__ uint32_t f2tf(float v) {
    uint32_t u;
    asm("cvt.rna.tf32.f32 %0, %1;" : "=r"(u) : "f"(v));
    return u;
}

__device__ __forceinline__ void mma_tf32(float* c,
                                         uint32_t a0, uint32_t a1, uint32_t a2, uint32_t a3,
                                         uint32_t b0, uint32_t b1) {
    asm volatile(
        "mma.sync.aligned.m16n8k8.row.col.f32.tf32.tf32.f32 "
        "{%0,%1,%2,%3}, {%4,%5,%6,%7}, {%8,%9}, {%0,%1,%2,%3};"
        : "+f"(c[0]), "+f"(c[1]), "+f"(c[2]), "+f"(c[3])
        : "r"(a0), "r"(a1), "r"(a2), "r"(a3), "r"(b0), "r"(b1));
}

__device__ __forceinline__ void mma_f16(float* c,
                                        uint32_t a0, uint32_t a1, uint32_t a2, uint32_t a3,
                                        uint32_t b0, uint32_t b1) {
    asm volatile(
        "mma.sync.aligned.m16n8k16.row.col.f32.f16.f16.f32 "
        "{%0,%1,%2,%3}, {%4,%5,%6,%7}, {%8,%9}, {%0,%1,%2,%3};"
        : "+f"(c[0]), "+f"(c[1]), "+f"(c[2]), "+f"(c[3])
        : "r"(a0), "r"(a1), "r"(a2), "r"(a3), "r"(b0), "r"(b1));
}

__device__ __forceinline__ unsigned ld_acq(const unsigned* p) {
    unsigned v;
    asm volatile("ld.acquire.gpu.global.u32 %0, [%1];" : "=r"(v) : "l"(p));
    return v;
}
__device__ __forceinline__ void st_rel(unsigned* p, unsigned v) {
    asm volatile("st.release.gpu.global.u32 [%0], %1;" :: "l"(p), "r"(v) : "memory");
}

__device__ __forceinline__ uint4 ldcg128(const void* p) {
    uint4 v;
    asm volatile("ld.global.cg.v4.u32 {%0,%1,%2,%3}, [%4];"
                 : "=r"(v.x), "=r"(v.y), "=r"(v.z), "=r"(v.w) : "l"(p));
    return v;
}

__device__ __forceinline__ uint32_t smem_u32(const void* p) {
    uint32_t a;
    asm("{ .reg .u64 t; cvta.to.shared.u64 t, %1; cvt.u32.u64 %0, t; }" : "=r"(a) : "l"(p));
    return a;
}

__device__ __forceinline__ float fsig(float x) { return 1.f / (1.f + __expf(-x)); }
__device__ __forceinline__ float ftanh(float x) {
    float e = __expf(-2.f * fabsf(x));
    float r = (1.f - e) / (1.f + e);
    return x < 0.f ? -r : r;
}

#define LDSM4(r0, r1, r2, r3, addr) \
    asm volatile("ldmatrix.sync.aligned.m8n8.x4.shared.b16 {%0,%1,%2,%3}, [%4];" \
                 : "=r"(r0), "=r"(r1), "=r"(r2), "=r"(r3) : "r"(addr))

// ---------------------------------------------------------------------------
// Kernel 1: xg = x @ Wi + b (tf32, known-good). Fused prep: Wh -> g_wrh
// (fp16, gate-interleaved: np = c*64 + nh*32 + g*8 + jj for
// col = g*1024 + c*16 + nh*8 + jj), h0 -> g_hf[0] (frag layout), reset flags.
// ---------------------------------------------------------------------------
__global__ __launch_bounds__(256) void xg_gemm_mma(const float* __restrict__ x,
                                                   const float* __restrict__ Wi,
                                                   const float* __restrict__ bias,
                                                   const float* __restrict__ Wh,
                                                   const float* __restrict__ h0) {
    {
        int gtid = (blockIdx.y * gridDim.x + blockIdx.x) * 256 + threadIdx.x;
        if (gtid < NCTA) g_flags[gtid * 64] = 0;
        if (gtid < 32768) {  // h0 -> frag layout, one half2 per thread
            int row = gtid >> 9;         // 0..63
            int col = (gtid & 511) * 2;  // even col
            int m = row >> 4, q = col >> 4, kin = col & 15;
            int lane = ((row & 7) << 2) | ((kin & 7) >> 1);
            int reg = ((row & 15) >> 3) | ((kin >> 3) << 1);
            __half2 hh = __floats2half2_rn(h0[row * HID + col], h0[row * HID + col + 1]);
            *(uint32_t*)((char*)g_hf + ((size_t)((m * 64 + q) * 32 + lane)) * 16 + reg * 4) =
                *(uint32_t*)&hh;
        }
#pragma unroll
        for (int e = 0; e < 2; e++) {
            int idx = e * (DIM * GATES / 2) + gtid;
            int col = idx & 4095, k = idx >> 12;
            int g = col >> 10, rem = col & 1023;
            int c = rem >> 4, r2 = rem & 15, nhp = r2 >> 3, jj = r2 & 7;
            int np = c * 64 + nhp * 32 + g * 8 + jj;
            g_wrh[(size_t)np * DIM + k] = __float2half_rn(Wh[idx]);
        }
    }

    __shared__ uint32_t As[128][36];
    __shared__ uint32_t Bs[32][132];

    int tid = threadIdx.x, wid = tid >> 5, lane = tid & 31;
    int gid = lane >> 2, tig = lane & 3;
    int bm = blockIdx.y * 128, bn = blockIdx.x * 128;
    int wrow = (wid & 3) * 32, wcol = (wid >> 2) * 64;

    float acc[2][8][4];
#pragma unroll
    for (int i = 0; i < 2; i++)
#pragma unroll
        for (int j = 0; j < 8; j++)
#pragma unroll
            for (int k = 0; k < 4; k++) acc[i][j][k] = 0.f;

    float4 pa[4], pb[4];

#pragma unroll
    for (int u = 0; u < 4; u++) {
        int s = u * 256 + tid, r = s >> 3, cc = (s & 7) * 4;
        pa[u] = *(const float4*)(x + (size_t)(bm + r) * DIM + cc);
    }
#pragma unroll
    for (int u = 0; u < 4; u++) {
        int s = u * 256 + tid, r = s >> 5, cc = (s & 31) * 4;
        pb[u] = *(const float4*)(Wi + (size_t)r * GATES + bn + cc);
    }

    for (int k0 = 0; k0 < DIM; k0 += 32) {
#pragma unroll
        for (int u = 0; u < 4; u++) {
            int s = u * 256 + tid, r = s >> 3, cc = (s & 7) * 4;
            As[r][cc + 0] = f2tf(pa[u].x); As[r][cc + 1] = f2tf(pa[u].y);
            As[r][cc + 2] = f2tf(pa[u].z); As[r][cc + 3] = f2tf(pa[u].w);
        }
#pragma unroll
        for (int u = 0; u < 4; u++) {
            int s = u * 256 + tid, r = s >> 5, cc = (s & 31) * 4;
            Bs[r][cc + 0] = f2tf(pb[u].x); Bs[r][cc + 1] = f2tf(pb[u].y);
            Bs[r][cc + 2] = f2tf(pb[u].z); Bs[r][cc + 3] = f2tf(pb[u].w);
        }
        __syncthreads();

        if (k0 + 32 < DIM) {
#pragma unroll
            for (int u = 0; u < 4; u++) {
                int s = u * 256 + tid, r = s >> 3, cc = (s & 7) * 4;
                pa[u] = *(const float4*)(x + (size_t)(bm + r) * DIM + k0 + 32 + cc);
            }
#pragma unroll
            for (int u = 0; u < 4; u++) {
                int s = u * 256 + tid, r = s >> 5, cc = (s & 31) * 4;
                pb[u] = *(const float4*)(Wi + (size_t)(k0 + 32 + r) * GATES + bn + cc);
            }
        }

#pragma unroll
        for (int kk = 0; kk < 4; kk++) {
            int kb = kk * 8;
            uint32_t a[2][4];
#pragma unroll
            for (int mf = 0; mf < 2; mf++) {
                int m = wrow + mf * 16 + gid;
                a[mf][0] = As[m][kb + tig];
                a[mf][1] = As[m + 8][kb + tig];
                a[mf][2] = As[m][kb + tig + 4];
                a[mf][3] = As[m + 8][kb + tig + 4];
            }
#pragma unroll
            for (int nf = 0; nf < 8; nf++) {
                uint32_t b0 = Bs[kb + tig][wcol + nf * 8 + gid];
                uint32_t b1 = Bs[kb + tig + 4][wcol + nf * 8 + gid];
                mma_tf32(acc[0][nf], a[0][0], a[0][1], a[0][2], a[0][3], b0, b1);
                mma_tf32(acc[1][nf], a[1][0], a[1][1], a[1][2], a[1][3], b0, b1);
            }
        }
        __syncthreads();
    }

#pragma unroll
    for (int mf = 0; mf < 2; mf++)
#pragma unroll
        for (int nf = 0; nf < 8; nf++) {
            int row = bm + wrow + mf * 16 + gid;
            int col = bn + wcol + nf * 8 + 2 * tig;
            float bv0 = bias[col], bv1 = bias[col + 1];
            g_xg[(size_t)row * GATES + col]           = acc[mf][nf][0] + bv0;
            g_xg[(size_t)row * GATES + col + 1]       = acc[mf][nf][1] + bv1;
            g_xg[(size_t)(row + 8) * GATES + col]     = acc[mf][nf][2] + bv0;
            g_xg[(size_t)(row + 8) * GATES + col + 1] = acc[mf][nf][3] + bv1;
        }
}

// ---------------------------------------------------------------------------
// Kernel 2: persistent recurrence, A direct-from-gmem in fragment layout.
// CTA (c = bid>>1, mg = bid&1): batch rows [mg*32,+32) x h-cols [c*16,+16) x
// 4 gates (N=64). 8 warps = 8-way K-split (warp ks owns k16 blocks
// q in [ks*8, ks*8+8)). Per-warp flag waits on its 8 producers only.
// B resident in smem (128 KB); reduce buffer 68 KB; no A smem tile.
// ---------------------------------------------------------------------------
#define BBYTES 131072                 // B: 64 n-rows x 2048 B, XOR swizzled
#define CHSZ   544                    // reduce chunk stride (512 data + pad)
#define RWSZ   (16 * CHSZ)            // per-warp reduce: 16 chunks (mf*8+nf)
#define REDOFF BBYTES
#define PERSIST_SMEM (REDOFF + 8 * RWSZ)   // 131072 + 69632 = 200704

__global__ __launch_bounds__(256, 1) void lstm_persist(const float* __restrict__ c0,
                                                       float* __restrict__ out) {
    extern __shared__ uint32_t sm[];
    char* smc = (char*)sm;
    uint32_t sbase = smem_u32(sm);

    int tid = threadIdx.x, wid = tid >> 5, lane = tid & 31;
    int cta = blockIdx.x;
    int c = cta >> 1, mg = cta & 1;
    int ks = wid;                      // this warp's K-eighth
    int n0 = c * 64;

    // ---- stationary B fill: 64 rows x 2048 B, XOR swizzled ----
#pragma unroll 4
    for (int u = 0; u < 32; u++) {
        int idx = u * 256 + tid;
        int n = idx >> 7, seg = idx & 127;
        uint4 v = *(const uint4*)((const char*)g_wrh + ((size_t)(n0 + n) * DIM + seg * 8) * 2);
        *(uint4*)(smc + n * 2048 + ((seg * 16) ^ ((n & 7) * 16))) = v;
    }

    // ---- B ldmatrix addressing (4 LDSM4 per k16: n-rows 0,16,32,48) ----
    int ri = lane & 7;
    uint32_t kbB = (uint32_t)(((lane >> 3) & 1) * 16);
    uint32_t bOff[4], bSw[4];
#pragma unroll
    for (int j = 0; j < 4; j++) {
        int nrow = j * 16 + ((lane >> 4) & 1) * 8 + ri;
        bOff[j] = (uint32_t)(nrow * 2048);
        bSw[j] = (uint32_t)((nrow & 7) * 16);
    }

    // ---- epilogue constants (every thread owns 2 h-cells) ----
    int rl = wid * 4 + (lane >> 3);        // local row 0..31
    int rgl = mg * 32 + rl;                // global batch row
    int nh_t = (lane >> 2) & 1;
    int jj0 = (lane & 3) * 2;
    int hc = c * 16 + nh_t * 8 + jj0;      // global h col (pair hc, hc+1)
    int mfE = rl >> 4, rf = rl & 15;
    int dlane = (rf & 7) * 4 + (jj0 >> 1);
    int fb = (rf >> 3) * 2;                // D-frag float index base
    int regE = (rf >> 3) | (nh_t << 1);    // A-frag reg index for h store
    uint32_t hfStoreOff =
        (uint32_t)(((mg * 2 + mfE) * 64 + c) * 32 + dlane) * 16 + regE * 4;

    float creg[2];
    creg[0] = c0[(size_t)rgl * HID + hc];
    creg[1] = c0[(size_t)rgl * HID + hc + 1];
    float xv[8];
#pragma unroll
    for (int g = 0; g < 4; g++) {
        xv[g * 2 + 0] = g_xg[(size_t)rgl * GATES + g * 1024 + hc];
        xv[g * 2 + 1] = g_xg[(size_t)rgl * GATES + g * 1024 + hc + 1];
    }
    __syncthreads();   // B resident

    for (int t = 0; t < T_STEPS; t++) {
        // ---- per-warp wait: only THIS warp's 8 producers ----
        if (t > 0) {
            if (lane < 8) {
                const unsigned* fp = &g_flags[(((ks * 8 + lane) << 1) | mg) << 6];
                while (ld_acq(fp) < (unsigned)t) { }
            }
            __syncwarp();
        }

        const char* hb = (const char*)g_hf + (size_t)(t & 1) * HFBYTES;

        // ---- A prefetch pipeline (depth 3), frags direct from gmem ----
        uint4 pa[3][2];
#pragma unroll
        for (int p = 0; p < 3; p++) {
            int q = ks * 8 + p;
#pragma unroll
            for (int mf = 0; mf < 2; mf++)
                pa[p][mf] = ldcg128(hb +
                    (size_t)(((mg * 2 + mf) * 64 + q) * 32 + lane) * 16);
        }

        float acc[2][8][4];
#pragma unroll
        for (int i = 0; i < 2; i++)
#pragma unroll
            for (int j = 0; j < 8; j++)
#pragma unroll
                for (int k = 0; k < 4; k++) acc[i][j][k] = 0.f;

#pragma unroll
        for (int kq = 0; kq < 8; kq++) {
            uint4 A0 = pa[kq % 3][0], A1 = pa[kq % 3][1];
            if (kq < 5) {
                int qn = ks * 8 + kq + 3;
#pragma unroll
                for (int mf = 0; mf < 2; mf++)
                    pa[kq % 3][mf] = ldcg128(hb +
                        (size_t)(((mg * 2 + mf) * 64 + qn) * 32 + lane) * 16);
            }
            int q = ks * 8 + kq;
            uint32_t kB = (uint32_t)(q * 32) + kbB;
            uint32_t bq[16];
#pragma unroll
            for (int j = 0; j < 4; j++)
                LDSM4(bq[j * 4], bq[j * 4 + 1], bq[j * 4 + 2], bq[j * 4 + 3],
                      sbase + bOff[j] + (kB ^ bSw[j]));
#pragma unroll
            for (int nf = 0; nf < 8; nf++) {
                mma_f16(acc[0][nf], A0.x, A0.y, A0.z, A0.w, bq[nf * 2], bq[nf * 2 + 1]);
                mma_f16(acc[1][nf], A1.x, A1.y, A1.z, A1.w, bq[nf * 2], bq[nf * 2 + 1]);
            }
        }

        // ---- partial stores: red[warp][mf*8+nf][lane] float4 ----
        {
            char* rp = smc + REDOFF + wid * RWSZ + lane * 16;
#pragma unroll
            for (int mf = 0; mf < 2; mf++)
#pragma unroll
                for (int nf = 0; nf < 8; nf++)
                    *(float4*)(rp + (mf * 8 + nf) * CHSZ) = *(const float4*)acc[mf][nf];
        }
        __syncthreads();

        // ---- reduce (8-way) + fused epilogue, ALL 256 threads ----
        float sg[4][2];
#pragma unroll
        for (int g = 0; g < 4; g++) { sg[g][0] = 0.f; sg[g][1] = 0.f; }
#pragma unroll
        for (int w = 0; w < 8; w++) {
            const char* rp = smc + REDOFF + w * RWSZ +
                             (mfE * 8 + nh_t * 4) * CHSZ + dlane * 16 + fb * 4;
#pragma unroll
            for (int g = 0; g < 4; g++) {
                float2 v = *(const float2*)(rp + g * CHSZ);
                sg[g][0] += v.x; sg[g][1] += v.y;
            }
        }

        float hv[2];
#pragma unroll
        for (int cc = 0; cc < 2; cc++) {
            float iv = fsig(sg[0][cc] + xv[cc]);
            float fv = fsig(sg[1][cc] + xv[2 + cc]);
            float gv = ftanh(sg[2][cc] + xv[4 + cc]);
            float ov = fsig(sg[3][cc] + xv[6 + cc]);
            float cv = fv * creg[cc] + iv * gv;
            creg[cc] = cv;
            hv[cc] = ov * ftanh(cv);
        }

        // h -> frag layout (one STG.32) for step t+1 consumers
        {
            __half2 hh = __floats2half2_rn(hv[0], hv[1]);
            *(uint32_t*)((char*)g_hf + (size_t)((t + 1) & 1) * HFBYTES + hfStoreOff) =
                *(uint32_t*)&hh;
        }
        __syncthreads();   // all epilogue stores done; red consumable next step
        if (tid == 0 && t + 1 < T_STEPS)
            st_rel(&g_flags[cta << 6], (unsigned)(t + 1));

        // fp32 output + next xg prefetch (off the release path)
        *(float2*)(out + (size_t)t * BATCH * HID + (size_t)rgl * HID + hc) =
            make_float2(hv[0], hv[1]);
        if (t + 1 < T_STEPS) {
            const float* xn = g_xg + (size_t)(t + 1) * BATCH * GATES + (size_t)rgl * GATES;
#pragma unroll
            for (int g = 0; g < 4; g++) {
                xv[g * 2 + 0] = xn[g * 1024 + hc];
                xv[g * 2 + 1] = xn[g * 1024 + hc + 1];
            }
        }
    }
}

// ---------------------------------------------------------------------------
extern "C" void kernel_launch(void* const* d_in, const int* in_sizes, int n_in,
                              void* d_out, int out_size) {
    const float* x  = (const float*)d_in[0];   // [T, B, D]
    const float* c0 = (const float*)d_in[1];   // [B, H]
    const float* h0 = (const float*)d_in[2];   // [B, H]
    const float* Wi = (const float*)d_in[3];   // [D, 4H]
    const float* Wh = (const float*)d_in[4];   // [H, 4H]
    const float* b  = (const float*)d_in[5];   // [4H]
    float* out = (float*)d_out;                // [T, B, H]

    cudaFuncSetAttribute(lstm_persist, cudaFuncAttributeMaxDynamicSharedMemorySize,
                         PERSIST_SMEM);

    // Input projection + fused prep (Wh->fp16 reorder, h0->frags, flag reset)
    dim3 g1(GATES / 128, (T_STEPS * BATCH) / 128);
    xg_gemm_mma<<<g1, 256>>>(x, Wi, b, Wh, h0);

    // Persistent recurrence: one launch, all 512 steps
    lstm_persist<<<NCTA, 256, PERSIST_SMEM>>>(c0, out);
}

// round 16
// speedup vs baseline: 1.5428x; 1.5346x over previous
#include <cuda_runtime.h>
#include <cuda_fp16.h>
#include <math.h>
#include <stdint.h>

#define T_STEPS 512
#define BATCH   64
#define DIM     1024
#define HID     1024
#define GATES   4096
#define NCTA    128

// Scratch (__device__ globals: allocation-free rule)
__device__ float    g_xg[(size_t)T_STEPS * BATCH * GATES]; // x@Wi + b (fp32)
__device__ __half   g_wrh[(size_t)GATES * DIM];            // Wh reordered [n'][k] (persist B)
__device__ uint32_t g_hf[2][4 * 64 * 32 * 4];              // h in A-frag layout, ping-pong
__device__ uint32_t g_xF[(size_t)T_STEPS * 4 * 64 * 32 * 4]; // x in A-frag layout (64MB)
__device__ uint32_t g_wiF[(size_t)512 * 64 * 32 * 2];      // Wi in B-frag layout (8MB)
__device__ unsigned g_flags[NCTA * 64];                    // per-CTA flag, 256B stride

#define HFBYTES 131072   // one g_hf buffer: 4 m-blocks x 64 q-blocks x 32 lanes x 16B

// ---------------------------------------------------------------------------
// Helpers
// ---------------------------------------------------------------------------
__device__ __forceinline__ void mma_f16(float* c,
                                        uint32_t a0, uint32_t a1, uint32_t a2, uint32_t a3,
                                        uint32_t b0, uint32_t b1) {
    asm volatile(
        "mma.sync.aligned.m16n8k16.row.col.f32.f16.f16.f32 "
        "{%0,%1,%2,%3}, {%4,%5,%6,%7}, {%8,%9}, {%0,%1,%2,%3};"
        : "+f"(c[0]), "+f"(c[1]), "+f"(c[2]), "+f"(c[3])
        : "r"(a0), "r"(a1), "r"(a2), "r"(a3), "r"(b0), "r"(b1));
}

__device__ __forceinline__ unsigned ld_acq(const unsigned* p) {
    unsigned v;
    asm volatile("ld.acquire.gpu.global.u32 %0, [%1];" : "=r"(v) : "l"(p));
    return v;
}
__device__ __forceinline__ void st_rel(unsigned* p, unsigned v) {
    asm volatile("st.release.gpu.global.u32 [%0], %1;" :: "l"(p), "r"(v) : "memory");
}

__device__ __forceinline__ uint4 ldcg128(const void* p) {
    uint4 v;
    asm volatile("ld.global.cg.v4.u32 {%0,%1,%2,%3}, [%4];"
                 : "=r"(v.x), "=r"(v.y), "=r"(v.z), "=r"(v.w) : "l"(p));
    return v;
}

__device__ __forceinline__ uint32_t smem_u32(const void* p) {
    uint32_t a;
    asm("{ .reg .u64 t; cvta.to.shared.u64 t, %1; cvt.u32.u64 %0, t; }" : "=r"(a) : "l"(p));
    return a;
}

__device__ __forceinline__ float fsig(float x) { return 1.f / (1.f + __expf(-x)); }
__device__ __forceinline__ float ftanh(float x) {
    float e = __expf(-2.f * fabsf(x));
    float r = (1.f - e) / (1.f + e);
    return x < 0.f ? -r : r;
}

#define LDSM4(r0, r1, r2, r3, addr) \
    asm volatile("ldmatrix.sync.aligned.m8n8.x4.shared.b16 {%0,%1,%2,%3}, [%4];" \
                 : "=r"(r0), "=r"(r1), "=r"(r2), "=r"(r3) : "r"(addr))

#define CP_ASYNC16(dst, src) \
    asm volatile("cp.async.cg.shared.global [%0], [%1], 16;" :: "r"(dst), "l"(src))
#define CP_ASYNC8(dst, src) \
    asm volatile("cp.async.ca.shared.global [%0], [%1], 8;" :: "r"(dst), "l"(src))
#define CP_COMMIT() asm volatile("cp.async.commit_group;" ::: "memory")
#define CP_WAIT0()  asm volatile("cp.async.wait_group 0;" ::: "memory")
#define CP_WAIT1()  asm volatile("cp.async.wait_group 1;" ::: "memory")

// ---------------------------------------------------------------------------
// Kernel 0: prep. Builds all precomputed layouts:
//  - g_xF : x -> fp16 A-frag layout (per t: [mb4][q64][lane32][16B])
//  - g_wiF: Wi -> fp16 B-frag layout ([nb512][q64][lane32][8B])
//  - g_wrh: Wh reordered [n'][k] fp16 (persist B; np = c*64+nh*32+g*8+jj)
//  - g_hf[0]: h0 -> A-frag layout
//  - g_flags reset
// Grid: 65536 x 256 (one thread per g_xF uint32 slot; extra work on low gtid).
// ---------------------------------------------------------------------------
__global__ __launch_bounds__(256) void prep_all(const float* __restrict__ x,
                                                const float* __restrict__ Wi,
                                                const float* __restrict__ Wh,
                                                const float* __restrict__ h0) {
    int gtid = blockIdx.x * 256 + threadIdx.x;   // 0 .. 16,777,215

    // ---- x -> g_xF (A-frag layout, same mapping proven for g_hf) ----
    {
        int t = gtid >> 15;            // 32768 uint32 slots per timestep
        int rem = gtid & 32767;
        int row = rem >> 9;            // batch row 0..63
        int col = (rem & 511) * 2;     // even k col
        int m = row >> 4, q = col >> 4, kin = col & 15;
        int lane = ((row & 7) << 2) | ((kin & 7) >> 1);
        int reg = ((row & 15) >> 3) | ((kin >> 3) << 1);
        const float* xs = x + (size_t)t * (BATCH * DIM) + row * DIM + col;
        __half2 hh = __floats2half2_rn(xs[0], xs[1]);
        *(uint32_t*)((char*)g_xF +
            ((size_t)(t * 256 + m * 64 + q) * 32 + lane) * 16 + reg * 4) = *(uint32_t*)&hh;
    }

    // ---- Wi -> g_wiF (B-frag layout: b0 = {B[k][n],B[k+1][n]}, n = lane>>2,
    //      kpair = lane&3, reg selects k%16 in [0,8) vs [8,16)) ----
    if (gtid < 2097152) {
        int reg = gtid & 1, lane = (gtid >> 1) & 31, q = (gtid >> 6) & 63, nb = gtid >> 12;
        int n = nb * 8 + (lane >> 2);
        int k = q * 16 + reg * 8 + (lane & 3) * 2;
        __half2 hh = __floats2half2_rn(Wi[(size_t)k * GATES + n],
                                       Wi[(size_t)(k + 1) * GATES + n]);
        *(uint32_t*)((char*)g_wiF +
            ((size_t)(nb * 64 + q) * 32 + lane) * 8 + reg * 4) = *(uint32_t*)&hh;
    }

    // ---- Wh -> g_wrh (persist stationary B) ----
    if (gtid < 2097152) {
#pragma unroll
        for (int e = 0; e < 2; e++) {
            int idx = e * (DIM * GATES / 2) + gtid;
            int col = idx & 4095, k = idx >> 12;
            int g = col >> 10, rem = col & 1023;
            int c = rem >> 4, r2 = rem & 15, nhp = r2 >> 3, jj = r2 & 7;
            int np = c * 64 + nhp * 32 + g * 8 + jj;
            g_wrh[(size_t)np * DIM + k] = __float2half_rn(Wh[idx]);
        }
    }

    // ---- h0 -> g_hf[0] (A-frag layout) ----
    if (gtid < 32768) {
        int row = gtid >> 9;
        int col = (gtid & 511) * 2;
        int m = row >> 4, q = col >> 4, kin = col & 15;
        int lane = ((row & 7) << 2) | ((kin & 7) >> 1);
        int reg = ((row & 15) >> 3) | ((kin >> 3) << 1);
        __half2 hh = __floats2half2_rn(h0[row * HID + col], h0[row * HID + col + 1]);
        *(uint32_t*)((char*)g_hf +
            ((size_t)(m * 64 + q) * 32 + lane) * 16 + reg * 4) = *(uint32_t*)&hh;
    }

    if (gtid < NCTA) g_flags[gtid << 6] = 0;
}

// ---------------------------------------------------------------------------
// Kernel 1: xg = x @ Wi + b via fp16 m16n8k16, frag-layout smem windows.
// CTA tile M128 x N128 (M = 2 timesteps x 64 batch). 8 warps: warp (mh =
// wid&1 -> t half / 4 m16 blocks, nq = wid>>1 -> 32 cols / 4 n8 blocks).
// Windows of 8 q-blocks staged by cp.async into 3 rotating smem buffers
// (A 32KB + B 32KB per buffer; gmem layout == smem layout == frag layout).
// ---------------------------------------------------------------------------
#define XG_WBYTES 65536                   // one window buffer: A 32KB + B 32KB
#define XG_SMEM   (3 * XG_WBYTES)         // 196608

__device__ __forceinline__ void xg_stage(uint32_t smbase, int buf, int my, int nx,
                                         int w, int tid) {
    uint32_t Ab = smbase + (uint32_t)buf * XG_WBYTES;
    uint32_t Bb = Ab + 32768;
    int q0 = w * 8;
    // A: 2048 slots x 16B  (slot s: mb8 = s>>8 (mh*4+mf), qq = (s>>5)&7, lane = s&31)
#pragma unroll
    for (int u = 0; u < 8; u++) {
        int s = u * 256 + tid;
        int mb8 = s >> 8, qq = (s >> 5) & 7, lane = s & 31;
        const char* src = (const char*)g_xF +
            ((size_t)((my * 2 + (mb8 >> 2)) * 256 + (mb8 & 3) * 64 + q0 + qq) * 32 + lane) * 16;
        CP_ASYNC16(Ab + (uint32_t)s * 16, src);
    }
    // B: 4096 slots x 8B   (slot s: nbq = s>>8 (nq*4+nf), qq = (s>>5)&7, lane = s&31)
#pragma unroll
    for (int u = 0; u < 16; u++) {
        int s = u * 256 + tid;
        int nbq = s >> 8, qq = (s >> 5) & 7, lane = s & 31;
        const char* src = (const char*)g_wiF +
            ((size_t)((nx * 16 + nbq) * 64 + q0 + qq) * 32 + lane) * 8;
        CP_ASYNC8(Bb + (uint32_t)s * 8, src);
    }
    CP_COMMIT();
}

__global__ __launch_bounds__(256) void xg_f16(const float* __restrict__ bias) {
    extern __shared__ char smc[];
    uint32_t smbase = smem_u32(smc);

    int tid = threadIdx.x, wid = tid >> 5, lane = tid & 31;
    int gid = lane >> 2, tig = lane & 3;
    int nx = blockIdx.x, my = blockIdx.y;
    int mh = wid & 1, nq = wid >> 1;

    float acc[4][4][4];
#pragma unroll
    for (int i = 0; i < 4; i++)
#pragma unroll
        for (int j = 0; j < 4; j++)
#pragma unroll
            for (int k = 0; k < 4; k++) acc[i][j][k] = 0.f;

    xg_stage(smbase, 0, my, nx, 0, tid);
    xg_stage(smbase, 1, my, nx, 1, tid);

    for (int w = 0; w < 8; w++) {
        if (w == 7) { CP_WAIT0(); } else { CP_WAIT1(); }
        __syncthreads();
        if (w < 6)
            xg_stage(smbase, (w + 2) % 3, my, nx, w + 2, tid);

        uint32_t Ab = smbase + (uint32_t)((w % 3) * XG_WBYTES);
        uint32_t Bb = Ab + 32768;
#pragma unroll
        for (int qq = 0; qq < 8; qq++) {
            uint4 av[4];
            uint2 bv[4];
#pragma unroll
            for (int mf = 0; mf < 4; mf++)
                av[mf] = *(const uint4*)(smc + (Ab - smbase) +
                    (((mh * 4 + mf) * 8 + qq) * 32 + lane) * 16);
#pragma unroll
            for (int nf = 0; nf < 4; nf++)
                bv[nf] = *(const uint2*)(smc + (Bb - smbase) +
                    (((nq * 4 + nf) * 8 + qq) * 32 + lane) * 8);
#pragma unroll
            for (int mf = 0; mf < 4; mf++)
#pragma unroll
                for (int nf = 0; nf < 4; nf++)
                    mma_f16(acc[mf][nf], av[mf].x, av[mf].y, av[mf].z, av[mf].w,
                            bv[nf].x, bv[nf].y);
        }
        __syncthreads();
    }

    // epilogue: D-frag rows gid/gid+8, cols tig*2/tig*2+1 (+bias), fp32 out
    int bn = nx * 128;
    float2 bval[4];
#pragma unroll
    for (int nf = 0; nf < 4; nf++)
        bval[nf] = *(const float2*)(bias + bn + nq * 32 + nf * 8 + tig * 2);

#pragma unroll
    for (int mf = 0; mf < 4; mf++) {
        int row = my * 128 + mh * 64 + mf * 16 + gid;
#pragma unroll
        for (int nf = 0; nf < 4; nf++) {
            int col = bn + nq * 32 + nf * 8 + tig * 2;
            *(float2*)(g_xg + (size_t)row * GATES + col) =
                make_float2(acc[mf][nf][0] + bval[nf].x, acc[mf][nf][1] + bval[nf].y);
            *(float2*)(g_xg + (size_t)(row + 8) * GATES + col) =
                make_float2(acc[mf][nf][2] + bval[nf].x, acc[mf][nf][3] + bval[nf].y);
        }
    }
}

// ---------------------------------------------------------------------------
// Kernel 2: persistent recurrence (UNCHANGED from R15 winner).
// ---------------------------------------------------------------------------
#define BBYTES 131072                 // B: 64 n-rows x 2048 B, XOR swizzled
#define CHSZ   544                    // reduce chunk stride (512 data + pad)
#define RWSZ   (16 * CHSZ)            // per-warp reduce: 16 chunks (mf*8+nf)
#define REDOFF BBYTES
#define PERSIST_SMEM (REDOFF + 8 * RWSZ)   // 200704

__global__ __launch_bounds__(256, 1) void lstm_persist(const float* __restrict__ c0,
                                                       float* __restrict__ out) {
    extern __shared__ uint32_t sm[];
    char* smc = (char*)sm;
    uint32_t sbase = smem_u32(sm);

    int tid = threadIdx.x, wid = tid >> 5, lane = tid & 31;
    int cta = blockIdx.x;
    int c = cta >> 1, mg = cta & 1;
    int ks = wid;
    int n0 = c * 64;

#pragma unroll 4
    for (int u = 0; u < 32; u++) {
        int idx = u * 256 + tid;
        int n = idx >> 7, seg = idx & 127;
        uint4 v = *(const uint4*)((const char*)g_wrh + ((size_t)(n0 + n) * DIM + seg * 8) * 2);
        *(uint4*)(smc + n * 2048 + ((seg * 16) ^ ((n & 7) * 16))) = v;
    }

    int ri = lane & 7;
    uint32_t kbB = (uint32_t)(((lane >> 3) & 1) * 16);
    uint32_t bOff[4], bSw[4];
#pragma unroll
    for (int j = 0; j < 4; j++) {
        int nrow = j * 16 + ((lane >> 4) & 1) * 8 + ri;
        bOff[j] = (uint32_t)(nrow * 2048);
        bSw[j] = (uint32_t)((nrow & 7) * 16);
    }

    int rl = wid * 4 + (lane >> 3);
    int rgl = mg * 32 + rl;
    int nh_t = (lane >> 2) & 1;
    int jj0 = (lane & 3) * 2;
    int hc = c * 16 + nh_t * 8 + jj0;
    int mfE = rl >> 4, rf = rl & 15;
    int dlane = (rf & 7) * 4 + (jj0 >> 1);
    int fb = (rf >> 3) * 2;
    int regE = (rf >> 3) | (nh_t << 1);
    uint32_t hfStoreOff =
        (uint32_t)(((mg * 2 + mfE) * 64 + c) * 32 + dlane) * 16 + regE * 4;

    float creg[2];
    creg[0] = c0[(size_t)rgl * HID + hc];
    creg[1] = c0[(size_t)rgl * HID + hc + 1];
    float xv[8];
#pragma unroll
    for (int g = 0; g < 4; g++) {
        xv[g * 2 + 0] = g_xg[(size_t)rgl * GATES + g * 1024 + hc];
        xv[g * 2 + 1] = g_xg[(size_t)rgl * GATES + g * 1024 + hc + 1];
    }
    __syncthreads();

    for (int t = 0; t < T_STEPS; t++) {
        if (t > 0) {
            if (lane < 8) {
                const unsigned* fp = &g_flags[(((ks * 8 + lane) << 1) | mg) << 6];
                while (ld_acq(fp) < (unsigned)t) { }
            }
            __syncwarp();
        }

        const char* hb = (const char*)g_hf + (size_t)(t & 1) * HFBYTES;

        uint4 pa[3][2];
#pragma unroll
        for (int p = 0; p < 3; p++) {
            int q = ks * 8 + p;
#pragma unroll
            for (int mf = 0; mf < 2; mf++)
                pa[p][mf] = ldcg128(hb +
                    (size_t)(((mg * 2 + mf) * 64 + q) * 32 + lane) * 16);
        }

        float acc[2][8][4];
#pragma unroll
        for (int i = 0; i < 2; i++)
#pragma unroll
            for (int j = 0; j < 8; j++)
#pragma unroll
                for (int k = 0; k < 4; k++) acc[i][j][k] = 0.f;

#pragma unroll
        for (int kq = 0; kq < 8; kq++) {
            uint4 A0 = pa[kq % 3][0], A1 = pa[kq % 3][1];
            if (kq < 5) {
                int qn = ks * 8 + kq + 3;
#pragma unroll
                for (int mf = 0; mf < 2; mf++)
                    pa[kq % 3][mf] = ldcg128(hb +
                        (size_t)(((mg * 2 + mf) * 64 + qn) * 32 + lane) * 16);
            }
            int q = ks * 8 + kq;
            uint32_t kB = (uint32_t)(q * 32) + kbB;
            uint32_t bq[16];
#pragma unroll
            for (int j = 0; j < 4; j++)
                LDSM4(bq[j * 4], bq[j * 4 + 1], bq[j * 4 + 2], bq[j * 4 + 3],
                      sbase + bOff[j] + (kB ^ bSw[j]));
#pragma unroll
            for (int nf = 0; nf < 8; nf++) {
                mma_f16(acc[0][nf], A0.x, A0.y, A0.z, A0.w, bq[nf * 2], bq[nf * 2 + 1]);
                mma_f16(acc[1][nf], A1.x, A1.y, A1.z, A1.w, bq[nf * 2], bq[nf * 2 + 1]);
            }
        }

        {
            char* rp = smc + REDOFF + wid * RWSZ + lane * 16;
#pragma unroll
            for (int mf = 0; mf < 2; mf++)
#pragma unroll
                for (int nf = 0; nf < 8; nf++)
                    *(float4*)(rp + (mf * 8 + nf) * CHSZ) = *(const float4*)acc[mf][nf];
        }
        __syncthreads();

        float sg[4][2];
#pragma unroll
        for (int g = 0; g < 4; g++) { sg[g][0] = 0.f; sg[g][1] = 0.f; }
#pragma unroll
        for (int w = 0; w < 8; w++) {
            const char* rp = smc + REDOFF + w * RWSZ +
                             (mfE * 8 + nh_t * 4) * CHSZ + dlane * 16 + fb * 4;
#pragma unroll
            for (int g = 0; g < 4; g++) {
                float2 v = *(const float2*)(rp + g * CHSZ);
                sg[g][0] += v.x; sg[g][1] += v.y;
            }
        }

        float hv[2];
#pragma unroll
        for (int cc = 0; cc < 2; cc++) {
            float iv = fsig(sg[0][cc] + xv[cc]);
            float fv = fsig(sg[1][cc] + xv[2 + cc]);
            float gv = ftanh(sg[2][cc] + xv[4 + cc]);
            float ov = fsig(sg[3][cc] + xv[6 + cc]);
            float cv = fv * creg[cc] + iv * gv;
            creg[cc] = cv;
            hv[cc] = ov * ftanh(cv);
        }

        {
            __half2 hh = __floats2half2_rn(hv[0], hv[1]);
            *(uint32_t*)((char*)g_hf + (size_t)((t + 1) & 1) * HFBYTES + hfStoreOff) =
                *(uint32_t*)&hh;
        }
        __syncthreads();
        if (tid == 0 && t + 1 < T_STEPS)
            st_rel(&g_flags[cta << 6], (unsigned)(t + 1));

        *(float2*)(out + (size_t)t * BATCH * HID + (size_t)rgl * HID + hc) =
            make_float2(hv[0], hv[1]);
        if (t + 1 < T_STEPS) {
            const float* xn = g_xg + (size_t)(t + 1) * BATCH * GATES + (size_t)rgl * GATES;
#pragma unroll
            for (int g = 0; g < 4; g++) {
                xv[g * 2 + 0] = xn[g * 1024 + hc];
                xv[g * 2 + 1] = xn[g * 1024 + hc + 1];
            }
        }
    }
}

// ---------------------------------------------------------------------------
extern "C" void kernel_launch(void* const* d_in, const int* in_sizes, int n_in,
                              void* d_out, int out_size) {
    const float* x  = (const float*)d_in[0];   // [T, B, D]
    const float* c0 = (const float*)d_in[1];   // [B, H]
    const float* h0 = (const float*)d_in[2];   // [B, H]
    const float* Wi = (const float*)d_in[3];   // [D, 4H]
    const float* Wh = (const float*)d_in[4];   // [H, 4H]
    const float* b  = (const float*)d_in[5];   // [4H]
    float* out = (float*)d_out;                // [T, B, H]

    cudaFuncSetAttribute(xg_f16, cudaFuncAttributeMaxDynamicSharedMemorySize, XG_SMEM);
    cudaFuncSetAttribute(lstm_persist, cudaFuncAttributeMaxDynamicSharedMemorySize,
                         PERSIST_SMEM);

    // Prep: all frag-layout conversions + flag reset
    prep_all<<<65536, 256>>>(x, Wi, Wh, h0);

    // Input projection: fp16 m16n8k16, cp.async windows
    xg_f16<<<dim3(32, 256), 256, XG_SMEM>>>(b);

    // Persistent recurrence (unchanged)
    lstm_persist<<<NCTA, 256, PERSIST_SMEM>>>(c0, out);
}